// round 10
// baseline (speedup 1.0000x reference)
#include <cuda_runtime.h>
#include <cstdint>
#include <math.h>

#define NEG_F (-3.402823466e+38f)   // jnp.finfo(float32).min == -FLT_MAX

// ---------------------------------------------------------------------------
// Champion configuration (R3): one block per row i of the N x N mask
// (N = t*h*w).
//   Phase 1: stream the whole row with -FLT_MAX (coalesced float4 stores).
//   Phase 2: after __syncthreads, threads 0..130 overwrite the <=131 masked
//            columns with 0.0f. These land on L2-dirty sectors written in
//            phase 1 by this same block, so they merge in L2: no extra DRAM
//            traffic, no separate scatter kernel.
// Masked columns per row:
//   - local window: dt,dh,dw in [-2,2]                      -> 125 candidates
//   - sparse pow2 {1,2,4} along exactly one axis (others 0) -> only +/-4 adds
//     new entries (1,2 lie inside the window)               ->   6 candidates
//
// Measured at 7.2 TB/s effective store throughput (~90% of 8 TB/s HBM spec).
// Tested and rejected alternatives: persistent single-wave grid (occ drop),
// cp.async.bulk S2G stores (LTS cap is path-independent), STG.256 (issue was
// never binding), per-chunk classify (ALU decode cost > scatter cost),
// 2 rows/block (neutral). This kernel is at the DRAM-write roofline.
// ---------------------------------------------------------------------------
__global__ void __launch_bounds__(256)
fused_mask_kernel(const int* __restrict__ tp, const int* __restrict__ hp,
                  const int* __restrict__ wp, float4* __restrict__ out4, int N) {
    const int i  = blockIdx.x;          // row index
    const int n4 = N >> 2;              // float4s per row

    // ---- Phase 1: fill row with -FLT_MAX ----
    float4* row = out4 + (size_t)i * (size_t)n4;
    const float4 v = make_float4(NEG_F, NEG_F, NEG_F, NEG_F);
    #pragma unroll 8
    for (int f = threadIdx.x; f < n4; f += 256) row[f] = v;

    __syncthreads();

    // ---- Phase 2: overwrite masked columns with 0.0f ----
    const int tid = threadIdx.x;
    if (tid < 131) {
        const int t = *tp;
        const int h = *hp;
        const int w = *wp;

        // decode row coordinate
        const int wi = i % w;
        const int ri = i / w;
        const int hi = ri % h;
        const int ti = ri / h;

        int dt, dh, dw;
        if (tid < 125) {
            dt = tid / 25 - 2;
            dh = (tid / 5) % 5 - 2;
            dw = tid % 5 - 2;
        } else {
            const int s    = tid - 125;        // 0..5
            const int axis = s >> 1;           // 0:t 1:h 2:w
            const int off  = (s & 1) ? 4 : -4;
            dt = (axis == 0) ? off : 0;
            dh = (axis == 1) ? off : 0;
            dw = (axis == 2) ? off : 0;
        }

        const int tj = ti + dt;
        const int hj = hi + dh;
        const int wj = wi + dw;
        if ((unsigned)tj < (unsigned)t &&
            (unsigned)hj < (unsigned)h &&
            (unsigned)wj < (unsigned)w) {
            const int j = (tj * h + hj) * w + wj;
            ((float*)row)[j] = 0.0f;
        }
    }
}

// ---------------------------------------------------------------------------
extern "C" void kernel_launch(void* const* d_in, const int* in_sizes, int n_in,
                              void* d_out, int out_size) {
    const int N = (int)(sqrt((double)out_size) + 0.5);   // out is N*N floats

    const int* tp = (const int*)d_in[0];
    const int* hp = (const int*)d_in[1];
    const int* wp = (const int*)d_in[2];

    fused_mask_kernel<<<N, 256>>>(tp, hp, wp, (float4*)d_out, N);
}

// round 11
// speedup vs baseline: 1.0023x; 1.0023x over previous
#include <cuda_runtime.h>
#include <cstdint>
#include <math.h>

#define NEG_F (-3.402823466e+38f)   // jnp.finfo(float32).min == -FLT_MAX

// ---------------------------------------------------------------------------
// Champion shape (R3) with hoisted phase-2 prologue: one block per row i of
// the N x N mask (N = t*h*w).
//   Prologue: threads 0..130 issue the t/h/w loads and fully decode their
//             candidate (dt,dh,dw) + row coords BEFORE the fill, so the
//             ~600-cycle load/div latency overlaps the store stream instead
//             of extending each CTA's tail after the barrier.
//   Phase 1:  stream the whole row with -FLT_MAX (coalesced float4 stores).
//   Phase 2:  after __syncthreads, threads 0..130 overwrite the <=131 masked
//             columns with 0.0f — sectors are still dirty in L2 from phase 1
//             of this same block, so the zeros merge: no extra DRAM traffic.
// Masked columns per row:
//   - local window: dt,dh,dw in [-2,2]                      -> 125 candidates
//   - sparse pow2 {1,2,4} along exactly one axis (others 0) -> only +/-4 adds
//     new entries (1,2 lie inside the window)               ->   6 candidates
//
// At the DRAM-write roofline: 7.2 TB/s effective (~90% of 8 TB/s spec).
// Rejected alternatives (all benched): persistent grid, cp.async.bulk S2G,
// STG.256, per-chunk classify, 2 rows/block.
// ---------------------------------------------------------------------------
__global__ void __launch_bounds__(256)
fused_mask_kernel(const int* __restrict__ tp, const int* __restrict__ hp,
                  const int* __restrict__ wp, float4* __restrict__ out4, int N) {
    const int i   = blockIdx.x;         // row index
    const int tid = threadIdx.x;
    const int n4  = N >> 2;             // float4s per row
    float4* row = out4 + (size_t)i * (size_t)n4;

    // ---- Prologue: decode candidate before the fill (tid < 131) ----
    int j = -1;                         // column to zero; -1 = none
    if (tid < 131) {
        const int t = *tp;
        const int h = *hp;
        const int w = *wp;

        const int wi = i % w;
        const int ri = i / w;
        const int hi = ri % h;
        const int ti = ri / h;

        int dt, dh, dw;
        if (tid < 125) {
            dt = tid / 25 - 2;
            dh = (tid / 5) % 5 - 2;
            dw = tid % 5 - 2;
        } else {
            const int s    = tid - 125;        // 0..5
            const int axis = s >> 1;           // 0:t 1:h 2:w
            const int off  = (s & 1) ? 4 : -4;
            dt = (axis == 0) ? off : 0;
            dh = (axis == 1) ? off : 0;
            dw = (axis == 2) ? off : 0;
        }

        const int tj = ti + dt;
        const int hj = hi + dh;
        const int wj = wi + dw;
        if ((unsigned)tj < (unsigned)t &&
            (unsigned)hj < (unsigned)h &&
            (unsigned)wj < (unsigned)w) {
            j = (tj * h + hj) * w + wj;
        }
    }

    // ---- Phase 1: fill row with -FLT_MAX ----
    const float4 v = make_float4(NEG_F, NEG_F, NEG_F, NEG_F);
    #pragma unroll 8
    for (int f = tid; f < n4; f += 256) row[f] = v;

    __syncthreads();

    // ---- Phase 2: single store per candidate thread ----
    if (j >= 0) ((float*)row)[j] = 0.0f;
}

// ---------------------------------------------------------------------------
extern "C" void kernel_launch(void* const* d_in, const int* in_sizes, int n_in,
                              void* d_out, int out_size) {
    const int N = (int)(sqrt((double)out_size) + 0.5);   // out is N*N floats

    const int* tp = (const int*)d_in[0];
    const int* hp = (const int*)d_in[1];
    const int* wp = (const int*)d_in[2];

    fused_mask_kernel<<<N, 256>>>(tp, hp, wp, (float4*)d_out, N);
}

// round 12
// speedup vs baseline: 1.0414x; 1.0390x over previous
#include <cuda_runtime.h>
#include <cstdint>
#include <math.h>

#define NEG_F (-3.402823466e+38f)   // jnp.finfo(float32).min == -FLT_MAX

// ---------------------------------------------------------------------------
// Champion shape + streaming fill: one block per row i of the N x N mask
// (N = t*h*w).
//   Prologue: threads 0..130 load t/h/w and fully decode their candidate
//             column BEFORE the fill (latency overlaps the store stream).
//   Phase 1:  stream the row with -FLT_MAX via st.global.cs (evict-first) —
//             the data has no reuse, so mark it streaming to let L2 schedule
//             writebacks early and keep the DRAM write pipe smoother.
//   Phase 2:  after __syncthreads, candidate threads store 0.0f with default
//             policy (merges in L2 when the line is still resident; bounded
//             RMW cost if it already drained).
// Masked columns per row:
//   - local window: dt,dh,dw in [-2,2]                      -> 125 candidates
//   - sparse pow2 {1,2,4} along exactly one axis (others 0) -> only +/-4 adds
//     new entries (1,2 lie inside the window)               ->   6 candidates
// ---------------------------------------------------------------------------
__global__ void __launch_bounds__(256)
fused_mask_kernel(const int* __restrict__ tp, const int* __restrict__ hp,
                  const int* __restrict__ wp, float4* __restrict__ out4, int N) {
    const int i   = blockIdx.x;         // row index
    const int tid = threadIdx.x;
    const int n4  = N >> 2;             // float4s per row
    float4* row = out4 + (size_t)i * (size_t)n4;

    // ---- Prologue: decode candidate before the fill (tid < 131) ----
    int j = -1;                         // column to zero; -1 = none
    if (tid < 131) {
        const int t = *tp;
        const int h = *hp;
        const int w = *wp;

        const int wi = i % w;
        const int ri = i / w;
        const int hi = ri % h;
        const int ti = ri / h;

        int dt, dh, dw;
        if (tid < 125) {
            dt = tid / 25 - 2;
            dh = (tid / 5) % 5 - 2;
            dw = tid % 5 - 2;
        } else {
            const int s    = tid - 125;        // 0..5
            const int axis = s >> 1;           // 0:t 1:h 2:w
            const int off  = (s & 1) ? 4 : -4;
            dt = (axis == 0) ? off : 0;
            dh = (axis == 1) ? off : 0;
            dw = (axis == 2) ? off : 0;
        }

        const int tj = ti + dt;
        const int hj = hi + dh;
        const int wj = wi + dw;
        if ((unsigned)tj < (unsigned)t &&
            (unsigned)hj < (unsigned)h &&
            (unsigned)wj < (unsigned)w) {
            j = (tj * h + hj) * w + wj;
        }
    }

    // ---- Phase 1: streaming fill with -FLT_MAX (evict-first) ----
    const float4 v = make_float4(NEG_F, NEG_F, NEG_F, NEG_F);
    #pragma unroll 8
    for (int f = tid; f < n4; f += 256) __stcs(row + f, v);

    __syncthreads();

    // ---- Phase 2: single store per candidate thread (default policy) ----
    if (j >= 0) ((float*)row)[j] = 0.0f;
}

// ---------------------------------------------------------------------------
extern "C" void kernel_launch(void* const* d_in, const int* in_sizes, int n_in,
                              void* d_out, int out_size) {
    const int N = (int)(sqrt((double)out_size) + 0.5);   // out is N*N floats

    const int* tp = (const int*)d_in[0];
    const int* hp = (const int*)d_in[1];
    const int* wp = (const int*)d_in[2];

    fused_mask_kernel<<<N, 256>>>(tp, hp, wp, (float4*)d_out, N);
}